// round 2
// baseline (speedup 1.0000x reference)
#include <cuda_runtime.h>
#include <cuda_fp16.h>
#include <cstdint>

// ============================================================
// FFTEmbedding as implicit-im2col GEMM (sm_100 baseline path:
// mma.sync m16n8k16 f16/f32 + ldmatrix; no tcgen05 on this target)
//
//   out[b,t,e] = sum_k window[t][k] * WeffT[e][k] + bias[e]
//   WeffT[e][k] = sum_{kk=0..128} cos(2pi kk k/256)*weight[e][kk]
//                                - sin(2pi kk k/256)*weight[e][129+kk]
//   window[t][k] = x_pad[t + k]  (Toeplitz -> A frags read from a
//   384-float segment; no A tile staging at all)
// ============================================================

#define B_SZ   16
#define T_SZ   8192
#define W_SZ   256
#define EMB    512
#define NFEAT  258

#define BM 128
#define BN 128
#define MTILES 1024           // (B*T)/BM
#define GRID   148
#define CTAS_PER_N 37         // GRID / 4 N-tiles
#define THREADS 256

#define PB 264                // B smem pitch in halfs (256 + 8 pad)
#define SMEM_B_BYTES (128 * PB * 2)            // 67584
#define SMEM_TOTAL   (SMEM_B_BYTES + 2 * 384 * 4)

// fp16 Weff^T, [EMB][W_SZ]
__device__ __half g_weffT[EMB * W_SZ];

__device__ __forceinline__ uint32_t smem_to_u32(const void* p) {
    uint32_t a;
    asm("{ .reg .u64 t; cvta.to.shared.u64 t, %1; cvt.u32.u64 %0, t; }" : "=r"(a) : "l"(p));
    return a;
}

__device__ __forceinline__ uint32_t ldcvt(const float* s) {
    __half2 h = __floats2half2_rn(s[0], s[1]);
    return *reinterpret_cast<uint32_t*>(&h);
}

__device__ __forceinline__ void mma16816(float* c, uint32_t a0, uint32_t a1,
                                         uint32_t a2, uint32_t a3,
                                         uint32_t b0, uint32_t b1) {
    asm volatile(
        "mma.sync.aligned.m16n8k16.row.col.f32.f16.f16.f32 "
        "{%0,%1,%2,%3}, {%4,%5,%6,%7}, {%8,%9}, {%0,%1,%2,%3};"
        : "+f"(c[0]), "+f"(c[1]), "+f"(c[2]), "+f"(c[3])
        : "r"(a0), "r"(a1), "r"(a2), "r"(a3), "r"(b0), "r"(b1));
}

__device__ __forceinline__ void ldmatrix_x4(uint32_t& r0, uint32_t& r1,
                                            uint32_t& r2, uint32_t& r3, uint32_t addr) {
    asm volatile("ldmatrix.sync.aligned.m8n8.x4.shared.b16 {%0,%1,%2,%3}, [%4];"
                 : "=r"(r0), "=r"(r1), "=r"(r2), "=r"(r3) : "r"(addr));
}

// ============================================================
// Kernel 1: Weff^T precompute (angle recurrence)
// ============================================================
__global__ void weff_kernel(const float* __restrict__ weight) {
    __shared__ float w1[129], w2[129];
    const int e = blockIdx.x;
    for (int f = threadIdx.x; f < NFEAT; f += 256) {
        float v = weight[e * NFEAT + f];
        if (f < 129) w1[f] = v; else w2[f - 129] = v;
    }
    __syncthreads();
    const int n = threadIdx.x;                // k position 0..255
    float s1, c1;
    sincospif((float)n / 128.0f, &s1, &c1);   // step angle 2*pi*n/256
    float acc = w1[0];
    float c = c1, s = s1;
    #pragma unroll 4
    for (int kk = 1; kk <= 128; kk++) {
        acc = fmaf(c, w1[kk], acc);
        acc = fmaf(-s, w2[kk], acc);
        float cn = fmaf(c, c1, -s * s1);
        float sn = fmaf(s, c1,  c * s1);
        c = cn; s = sn;
    }
    g_weffT[e * W_SZ + n] = __float2half_rn(acc);
}

// ============================================================
// Kernel 2: persistent GEMM, grid=148, 256 threads
// warp grid 4(m) x 2(n); warp tile 32m x 64n
// ============================================================
__global__ void __launch_bounds__(THREADS, 1) fft_gemm_kernel(
    const float* __restrict__ x,
    const float* __restrict__ bias,
    float* __restrict__ out)
{
    extern __shared__ char smem[];
    __half* Bs = (__half*)smem;
    float (*seg)[384] = (float(*)[384])(smem + SMEM_B_BYTES);

    const int tid  = threadIdx.x;
    const int wid  = tid >> 5;
    const int lane = tid & 31;
    const int q    = lane & 3;        // thread-in-group
    const int r4   = lane >> 2;       // group id (row within 8)
    const int wm   = (wid & 3) * 32;  // warp m offset
    const int wn   = (wid >> 2) * 64; // warp n offset
    const int ntile = (int)(blockIdx.x & 3);
    const int e0    = ntile * BN;

    // ---- load B tile (WeffT rows e0..e0+127) once ----
    for (int u = tid; u < 4096; u += THREADS) {
        int r  = u >> 5;          // e row 0..127
        int ch = u & 31;          // 16B chunk along k
        uint4 v = *reinterpret_cast<const uint4*>(&g_weffT[(e0 + r) * W_SZ + ch * 8]);
        *reinterpret_cast<uint4*>(Bs + r * PB + ch * 8) = v;
    }

    // ---- per-thread bias registers ----
    float bias0[8], bias1[8];
    #pragma unroll
    for (int nt = 0; nt < 8; nt++) {
        int col = e0 + wn + nt * 8 + 2 * q;
        bias0[nt] = bias[col];
        bias1[nt] = bias[col + 1];
    }

    // ---- ldmatrix base address for B fragments ----
    // lanes 0-7: mat(n0,k0)   8-15: mat(n0,k0+8)
    // lanes16-23: mat(n0+8,k0) 24-31: mat(n0+8,k0+8)
    const uint32_t sbB = smem_to_u32(Bs);
    const int brow = wn + (lane & 7) + ((lane & 16) ? 8 : 0);
    const int bkof = (lane & 8) ? 8 : 0;
    const uint32_t baddr0 = sbB + (uint32_t)(brow * PB + bkof) * 2u;

    // ---- initial segment load for first M-tile ----
    const int mt0 = (int)(blockIdx.x >> 2);
    {
        int bidx = mt0 >> 6, t0 = (mt0 & 63) * BM;
        int gx0 = t0 + tid - (W_SZ - 1);
        seg[0][tid] = (gx0 >= 0) ? x[bidx * T_SZ + gx0] : 0.0f;
        if (tid < 128) {
            int j = 256 + tid;
            int gx1 = t0 + j - (W_SZ - 1);
            seg[0][j] = (j < 383 && gx1 >= 0) ? x[bidx * T_SZ + gx1] : 0.0f;
        }
    }
    __syncthreads();

    int pb = 0;
    for (int mt = mt0; mt < MTILES; mt += CTAS_PER_N, pb ^= 1) {
        // ---- prefetch next segment into registers ----
        const int mtn = mt + CTAS_PER_N;
        float p0 = 0.0f, p1 = 0.0f;
        if (mtn < MTILES) {
            int bidx = mtn >> 6, t0 = (mtn & 63) * BM;
            int gx0 = t0 + tid - (W_SZ - 1);
            if (gx0 >= 0) p0 = x[bidx * T_SZ + gx0];
            if (tid < 128) {
                int j = 256 + tid;
                int gx1 = t0 + j - (W_SZ - 1);
                if (j < 383 && gx1 >= 0) p1 = x[bidx * T_SZ + gx1];
            }
        }

        // ---- MMA mainloop over K=256 (16 k-steps) ----
        float acc[2][8][4];
        #pragma unroll
        for (int m = 0; m < 2; m++)
            #pragma unroll
            for (int n = 0; n < 8; n++)
                #pragma unroll
                for (int c = 0; c < 4; c++) acc[m][n][c] = 0.0f;

        const float* sg = seg[pb];
        const int base0 = wm + r4 + 2 * q;        // m-tile 0
        const int base1 = base0 + 16;             // m-tile 1
        uint32_t alo0 = ldcvt(sg + base0);
        uint32_t alo1 = ldcvt(sg + base1);

        #pragma unroll
        for (int ks = 0; ks < 16; ks++) {
            const int ko = ks * 16;
            uint32_t amid0 = ldcvt(sg + base0 + ko + 8);
            uint32_t ahi0  = ldcvt(sg + base0 + ko + 16);
            uint32_t amid1 = ldcvt(sg + base1 + ko + 8);
            uint32_t ahi1  = ldcvt(sg + base1 + ko + 16);

            #pragma unroll
            for (int p = 0; p < 4; p++) {
                uint32_t b0, b1, b2, b3;
                ldmatrix_x4(b0, b1, b2, b3,
                            baddr0 + (uint32_t)(p * 16 * PB * 2 + ks * 32));
                mma16816(acc[0][2*p],   alo0, amid0, amid0, ahi0, b0, b1);
                mma16816(acc[0][2*p+1], alo0, amid0, amid0, ahi0, b2, b3);
                mma16816(acc[1][2*p],   alo1, amid1, amid1, ahi1, b0, b1);
                mma16816(acc[1][2*p+1], alo1, amid1, amid1, ahi1, b2, b3);
            }
            alo0 = ahi0;
            alo1 = ahi1;
        }

        // ---- store prefetched segment into alternate buffer ----
        if (mtn < MTILES) {
            seg[pb ^ 1][tid] = p0;
            if (tid < 128) seg[pb ^ 1][256 + tid] = p1;
        }

        // ---- epilogue: bias + vectorized STG ----
        const size_t rowb = (size_t)mt * BM + (size_t)(wm + r4);
        #pragma unroll
        for (int m = 0; m < 2; m++) {
            float* o0 = out + (rowb + m * 16) * EMB + e0 + wn + 2 * q;
            float* o1 = o0 + 8 * EMB;
            #pragma unroll
            for (int nt = 0; nt < 8; nt++) {
                float2 v0 = make_float2(acc[m][nt][0] + bias0[nt],
                                        acc[m][nt][1] + bias1[nt]);
                float2 v1 = make_float2(acc[m][nt][2] + bias0[nt],
                                        acc[m][nt][3] + bias1[nt]);
                *reinterpret_cast<float2*>(o0 + nt * 8) = v0;
                *reinterpret_cast<float2*>(o1 + nt * 8) = v1;
            }
        }
        __syncthreads();   // seg[pb^1] visible; seg[pb] free for next prefetch
    }
}

// ============================================================
extern "C" void kernel_launch(void* const* d_in, const int* in_sizes, int n_in,
                              void* d_out, int out_size) {
    const float* x  = nullptr;
    const float* wt = nullptr;
    const float* bs = nullptr;
    for (int i = 0; i < n_in; i++) {
        if (in_sizes[i] == B_SZ * T_SZ)        x  = (const float*)d_in[i];
        else if (in_sizes[i] == EMB * NFEAT)   wt = (const float*)d_in[i];
        else if (in_sizes[i] == EMB)           bs = (const float*)d_in[i];
    }

    weff_kernel<<<EMB, 256>>>(wt);

    cudaFuncSetAttribute(fft_gemm_kernel,
                         cudaFuncAttributeMaxDynamicSharedMemorySize, SMEM_TOTAL);
    fft_gemm_kernel<<<GRID, THREADS, SMEM_TOTAL>>>(x, bs, (float*)d_out);
}

// round 3
// speedup vs baseline: 1.0184x; 1.0184x over previous
#include <cuda_runtime.h>
#include <cuda_fp16.h>
#include <cstdint>

// ============================================================
// FFTEmbedding as implicit-im2col GEMM (sm_100 legacy-HMMA path)
//   out = A(131072x256 Toeplitz windows) @ WeffT(512x256)^T + bias
// R3: 2 CTAs/SM (grid 296) + m-heavy warp tiles (128m x 16n):
//     B smem traffic 1x tile/iter, A from sliding 17-reg Toeplitz window.
// ============================================================

#define B_SZ   16
#define T_SZ   8192
#define W_SZ   256
#define EMB    512
#define NFEAT  258

#define BM 128
#define BN 128
#define MTILES 1024           // (B*T)/BM
#define GRID   296            // 2 CTAs per SM
#define CTAS_PER_N 74         // GRID / 4 N-tiles
#define THREADS 256

#define PB 264                // B smem pitch in halfs (256 + 8 pad)
#define SMEM_B_BYTES (128 * PB * 2)            // 67584
#define SMEM_TOTAL   (SMEM_B_BYTES + 2 * 384 * 4)

// fp16 Weff^T, [EMB][W_SZ]
__device__ __half g_weffT[EMB * W_SZ];

__device__ __forceinline__ uint32_t smem_to_u32(const void* p) {
    uint32_t a;
    asm("{ .reg .u64 t; cvta.to.shared.u64 t, %1; cvt.u32.u64 %0, t; }" : "=r"(a) : "l"(p));
    return a;
}

__device__ __forceinline__ uint32_t ldcvt(const float* s) {
    __half2 h = __floats2half2_rn(s[0], s[1]);
    return *reinterpret_cast<uint32_t*>(&h);
}

__device__ __forceinline__ void mma16816(float* c, uint32_t a0, uint32_t a1,
                                         uint32_t a2, uint32_t a3,
                                         uint32_t b0, uint32_t b1) {
    asm volatile(
        "mma.sync.aligned.m16n8k16.row.col.f32.f16.f16.f32 "
        "{%0,%1,%2,%3}, {%4,%5,%6,%7}, {%8,%9}, {%0,%1,%2,%3};"
        : "+f"(c[0]), "+f"(c[1]), "+f"(c[2]), "+f"(c[3])
        : "r"(a0), "r"(a1), "r"(a2), "r"(a3), "r"(b0), "r"(b1));
}

__device__ __forceinline__ void ldmatrix_x4(uint32_t& r0, uint32_t& r1,
                                            uint32_t& r2, uint32_t& r3, uint32_t addr) {
    asm volatile("ldmatrix.sync.aligned.m8n8.x4.shared.b16 {%0,%1,%2,%3}, [%4];"
                 : "=r"(r0), "=r"(r1), "=r"(r2), "=r"(r3) : "r"(addr));
}

// ============================================================
// Kernel 1: Weff^T precompute (angle recurrence)
// ============================================================
__global__ void weff_kernel(const float* __restrict__ weight) {
    __shared__ float w1[129], w2[129];
    const int e = blockIdx.x;
    for (int f = threadIdx.x; f < NFEAT; f += 256) {
        float v = weight[e * NFEAT + f];
        if (f < 129) w1[f] = v; else w2[f - 129] = v;
    }
    __syncthreads();
    const int n = threadIdx.x;                // k position 0..255
    float s1, c1;
    sincospif((float)n / 128.0f, &s1, &c1);   // step angle 2*pi*n/256
    float acc = w1[0];
    float c = c1, s = s1;
    #pragma unroll 4
    for (int kk = 1; kk <= 128; kk++) {
        acc = fmaf(c, w1[kk], acc);
        acc = fmaf(-s, w2[kk], acc);
        float cn = fmaf(c, c1, -s * s1);
        float sn = fmaf(s, c1,  c * s1);
        c = cn; s = sn;
    }
    g_weffT[e * W_SZ + n] = __float2half_rn(acc);
}

// ============================================================
// Kernel 2: persistent GEMM, grid=296 (2 CTAs/SM), 256 threads
// warp tile: 128m x 16n  (warp wid owns n-slice wid*16)
// ============================================================
__global__ void __launch_bounds__(THREADS, 2) fft_gemm_kernel(
    const float* __restrict__ x,
    const float* __restrict__ bias,
    float* __restrict__ out)
{
    extern __shared__ char smem[];
    __half* Bs = (__half*)smem;
    float (*seg)[384] = (float(*)[384])(smem + SMEM_B_BYTES);

    const int tid  = threadIdx.x;
    const int wid  = tid >> 5;
    const int lane = tid & 31;
    const int q    = lane & 3;        // col-pair within n8 tile
    const int r4   = lane >> 2;       // row within 8
    const int ntile = (int)(blockIdx.x & 3);
    const int e0    = ntile * BN;

    // ---- load B tile (WeffT rows e0..e0+127) once ----
    for (int u = tid; u < 4096; u += THREADS) {
        int r  = u >> 5;          // e row 0..127
        int ch = u & 31;          // 16B chunk along k
        uint4 v = *reinterpret_cast<const uint4*>(&g_weffT[(e0 + r) * W_SZ + ch * 8]);
        *reinterpret_cast<uint4*>(Bs + r * PB + ch * 8) = v;
    }

    // ---- per-thread bias registers (4 cols: n-tile 0/1, col 2q/2q+1) ----
    const int colb = e0 + wid * 16 + 2 * q;
    float bias00 = bias[colb],     bias01 = bias[colb + 1];
    float bias10 = bias[colb + 8], bias11 = bias[colb + 9];

    // ---- ldmatrix base address for this warp's 16-col B slice ----
    const uint32_t sbB = smem_to_u32(Bs);
    const int brow = wid * 16 + (lane & 7) + ((lane & 16) ? 8 : 0);
    const int bkof = (lane & 8) ? 8 : 0;
    const uint32_t baddr0 = sbB + (uint32_t)(brow * PB + bkof) * 2u;

    // ---- initial segment load for first M-tile ----
    const int mt0 = (int)(blockIdx.x >> 2);
    {
        int bidx = mt0 >> 6, t0 = (mt0 & 63) * BM;
        int gx0 = t0 + tid - (W_SZ - 1);
        seg[0][tid] = (gx0 >= 0) ? x[bidx * T_SZ + gx0] : 0.0f;
        if (tid < 128) {
            int j = 256 + tid;
            int gx1 = t0 + j - (W_SZ - 1);
            seg[0][j] = (j < 383 && gx1 >= 0) ? x[bidx * T_SZ + gx1] : 0.0f;
        }
    }
    __syncthreads();

    int pb = 0;
    for (int mt = mt0; mt < MTILES; mt += CTAS_PER_N, pb ^= 1) {
        // ---- prefetch next segment into registers ----
        const int mtn = mt + CTAS_PER_N;
        float p0 = 0.0f, p1 = 0.0f;
        if (mtn < MTILES) {
            int bidx = mtn >> 6, t0 = (mtn & 63) * BM;
            int gx0 = t0 + tid - (W_SZ - 1);
            if (gx0 >= 0) p0 = x[bidx * T_SZ + gx0];
            if (tid < 128) {
                int j = 256 + tid;
                int gx1 = t0 + j - (W_SZ - 1);
                if (j < 383 && gx1 >= 0) p1 = x[bidx * T_SZ + gx1];
            }
        }

        // ---- MMA mainloop: K=256 (16 k-steps), 8 m-tiles, 2 n-tiles ----
        float acc[8][2][4];
        #pragma unroll
        for (int m = 0; m < 8; m++)
            #pragma unroll
            for (int n = 0; n < 2; n++)
                #pragma unroll
                for (int c = 0; c < 4; c++) acc[m][n][c] = 0.0f;

        const float* sg = seg[pb];
        const int base0 = r4 + 2 * q;

        // Toeplitz A: av[j] = half2(seg[base0 + 16*ks + 8j .. +1])
        uint32_t av[17];
        #pragma unroll
        for (int j = 0; j < 17; j++) av[j] = ldcvt(sg + base0 + 8 * j);

        #pragma unroll
        for (int ks = 0; ks < 16; ks++) {
            uint32_t b0, b1, b2, b3;
            ldmatrix_x4(b0, b1, b2, b3, baddr0 + (uint32_t)(ks * 32));
            #pragma unroll
            for (int m = 0; m < 8; m++) {
                mma16816(acc[m][0], av[2*m], av[2*m+1], av[2*m+1], av[2*m+2], b0, b1);
                mma16816(acc[m][1], av[2*m], av[2*m+1], av[2*m+1], av[2*m+2], b2, b3);
            }
            if (ks < 15) {
                #pragma unroll
                for (int j = 0; j < 15; j++) av[j] = av[j + 2];
                av[15] = ldcvt(sg + base0 + 16 * (ks + 1) + 120);
                av[16] = ldcvt(sg + base0 + 16 * (ks + 1) + 128);
            }
        }

        // ---- store prefetched segment into alternate buffer ----
        if (mtn < MTILES) {
            seg[pb ^ 1][tid] = p0;
            if (tid < 128) seg[pb ^ 1][256 + tid] = p1;
        }

        // ---- epilogue: bias + vectorized STG ----
        const size_t rowb = (size_t)mt * BM + (size_t)r4;
        #pragma unroll
        for (int m = 0; m < 8; m++) {
            float* o0 = out + (rowb + 16 * m) * EMB + colb;
            float* o1 = o0 + 8 * EMB;
            {
                float2 v0 = make_float2(acc[m][0][0] + bias00, acc[m][0][1] + bias01);
                float2 v1 = make_float2(acc[m][0][2] + bias00, acc[m][0][3] + bias01);
                *reinterpret_cast<float2*>(o0) = v0;
                *reinterpret_cast<float2*>(o1) = v1;
            }
            {
                float2 v0 = make_float2(acc[m][1][0] + bias10, acc[m][1][1] + bias11);
                float2 v1 = make_float2(acc[m][1][2] + bias10, acc[m][1][3] + bias11);
                *reinterpret_cast<float2*>(o0 + 8) = v0;
                *reinterpret_cast<float2*>(o1 + 8) = v1;
            }
        }
        __syncthreads();   // seg[pb^1] visible; seg[pb] free for next prefetch
    }
}

// ============================================================
extern "C" void kernel_launch(void* const* d_in, const int* in_sizes, int n_in,
                              void* d_out, int out_size) {
    const float* x  = nullptr;
    const float* wt = nullptr;
    const float* bs = nullptr;
    for (int i = 0; i < n_in; i++) {
        if (in_sizes[i] == B_SZ * T_SZ)        x  = (const float*)d_in[i];
        else if (in_sizes[i] == EMB * NFEAT)   wt = (const float*)d_in[i];
        else if (in_sizes[i] == EMB)           bs = (const float*)d_in[i];
    }

    weff_kernel<<<EMB, 256>>>(wt);

    cudaFuncSetAttribute(fft_gemm_kernel,
                         cudaFuncAttributeMaxDynamicSharedMemorySize, SMEM_TOTAL);
    fft_gemm_kernel<<<GRID, THREADS, SMEM_TOTAL>>>(x, bs, (float*)d_out);
}

// round 4
// speedup vs baseline: 1.0731x; 1.0537x over previous
#include <cuda_runtime.h>
#include <cuda_fp16.h>
#include <cstdint>

// ============================================================
// FFTEmbedding as implicit-im2col GEMM (sm_100 legacy-HMMA path)
//   out = A(131072x256 Toeplitz windows) @ WeffT(512x256)^T + bias
// R4: permuted-B columns so epilogue uses STG.128; discriminating
//     test of the 512-MAC/cyc/SM legacy-HMMA ceiling theory.
// ============================================================

#define B_SZ   16
#define T_SZ   8192
#define W_SZ   256
#define EMB    512
#define NFEAT  258

#define BM 128
#define BN 128
#define MTILES 1024           // (B*T)/BM
#define GRID   296            // 2 CTAs per SM
#define CTAS_PER_N 74         // GRID / 4 N-tiles
#define THREADS 256

#define PB 264                // B smem pitch in halfs (256 + 8 pad)
#define SMEM_B_BYTES (128 * PB * 2)            // 67584
#define SMEM_TOTAL   (SMEM_B_BYTES + 2 * 384 * 4)

// fp16 Weff^T, [EMB][W_SZ]
__device__ __half g_weffT[EMB * W_SZ];

__device__ __forceinline__ uint32_t smem_to_u32(const void* p) {
    uint32_t a;
    asm("{ .reg .u64 t; cvta.to.shared.u64 t, %1; cvt.u32.u64 %0, t; }" : "=r"(a) : "l"(p));
    return a;
}

__device__ __forceinline__ uint32_t ldcvt(const float* s) {
    __half2 h = __floats2half2_rn(s[0], s[1]);
    return *reinterpret_cast<uint32_t*>(&h);
}

__device__ __forceinline__ void mma16816(float* c, uint32_t a0, uint32_t a1,
                                         uint32_t a2, uint32_t a3,
                                         uint32_t b0, uint32_t b1) {
    asm volatile(
        "mma.sync.aligned.m16n8k16.row.col.f32.f16.f16.f32 "
        "{%0,%1,%2,%3}, {%4,%5,%6,%7}, {%8,%9}, {%0,%1,%2,%3};"
        : "+f"(c[0]), "+f"(c[1]), "+f"(c[2]), "+f"(c[3])
        : "r"(a0), "r"(a1), "r"(a2), "r"(a3), "r"(b0), "r"(b1));
}

__device__ __forceinline__ void ldmatrix_x4(uint32_t& r0, uint32_t& r1,
                                            uint32_t& r2, uint32_t& r3, uint32_t addr) {
    asm volatile("ldmatrix.sync.aligned.m8n8.x4.shared.b16 {%0,%1,%2,%3}, [%4];"
                 : "=r"(r0), "=r"(r1), "=r"(r2), "=r"(r3) : "r"(addr));
}

// Column permutation within each warp's 16-col slice: B-slice row s holds
// the Weff row for output column perm(s), chosen so thread q's four
// accumulator columns {2q,2q+1 | tile0; 2q,2q+1 | tile1} land on
// contiguous output columns 4q..4q+3 (enables STG.128).
__device__ __host__ __forceinline__ int permcol(int s) {
    return (s < 8) ? ((s & 1) ? 2 * s - 1 : 2 * s)
                   : ((s & 1) ? 2 * s - 15 : 2 * s - 14);
}

// ============================================================
// Kernel 1: Weff^T precompute (angle recurrence)
// ============================================================
__global__ void weff_kernel(const float* __restrict__ weight) {
    __shared__ float w1[129], w2[129];
    const int e = blockIdx.x;
    for (int f = threadIdx.x; f < NFEAT; f += 256) {
        float v = weight[e * NFEAT + f];
        if (f < 129) w1[f] = v; else w2[f - 129] = v;
    }
    __syncthreads();
    const int n = threadIdx.x;                // k position 0..255
    float s1, c1;
    sincospif((float)n / 128.0f, &s1, &c1);   // step angle 2*pi*n/256
    float acc = w1[0];
    float c = c1, s = s1;
    #pragma unroll 4
    for (int kk = 1; kk <= 128; kk++) {
        acc = fmaf(c, w1[kk], acc);
        acc = fmaf(-s, w2[kk], acc);
        float cn = fmaf(c, c1, -s * s1);
        float sn = fmaf(s, c1,  c * s1);
        c = cn; s = sn;
    }
    g_weffT[e * W_SZ + n] = __float2half_rn(acc);
}

// ============================================================
// Kernel 2: persistent GEMM, grid=296 (2 CTAs/SM), 256 threads
// warp tile: 128m x 16n  (warp wid owns n-slice wid*16)
// ============================================================
__global__ void __launch_bounds__(THREADS, 2) fft_gemm_kernel(
    const float* __restrict__ x,
    const float* __restrict__ bias,
    float* __restrict__ out)
{
    extern __shared__ char smem[];
    __half* Bs = (__half*)smem;
    float (*seg)[384] = (float(*)[384])(smem + SMEM_B_BYTES);

    const int tid  = threadIdx.x;
    const int wid  = tid >> 5;
    const int lane = tid & 31;
    const int q    = lane & 3;        // col-pair within n8 tile
    const int r4   = lane >> 2;       // row within 8
    const int ntile = (int)(blockIdx.x & 3);
    const int e0    = ntile * BN;

    // ---- load B tile (WeffT rows e0..e0+127), permuted within slices ----
    for (int u = tid; u < 4096; u += THREADS) {
        int r  = u >> 5;          // Bs row 0..127
        int ch = u & 31;          // 16B chunk along k
        int esrc = e0 + (r & ~15) + permcol(r & 15);
        uint4 v = *reinterpret_cast<const uint4*>(&g_weffT[esrc * W_SZ + ch * 8]);
        *reinterpret_cast<uint4*>(Bs + r * PB + ch * 8) = v;
    }

    // ---- per-thread bias: 4 contiguous cols ----
    const int colb = e0 + wid * 16 + 4 * q;
    const float4 bias4 = *reinterpret_cast<const float4*>(bias + colb);

    // ---- ldmatrix base address for this warp's 16-row B slice ----
    const uint32_t sbB = smem_to_u32(Bs);
    const int brow = wid * 16 + (lane & 7) + ((lane & 16) ? 8 : 0);
    const int bkof = (lane & 8) ? 8 : 0;
    const uint32_t baddr0 = sbB + (uint32_t)(brow * PB + bkof) * 2u;

    // ---- initial segment load for first M-tile ----
    const int mt0 = (int)(blockIdx.x >> 2);
    {
        int bidx = mt0 >> 6, t0 = (mt0 & 63) * BM;
        int gx0 = t0 + tid - (W_SZ - 1);
        seg[0][tid] = (gx0 >= 0) ? x[bidx * T_SZ + gx0] : 0.0f;
        if (tid < 128) {
            int j = 256 + tid;
            int gx1 = t0 + j - (W_SZ - 1);
            seg[0][j] = (j < 383 && gx1 >= 0) ? x[bidx * T_SZ + gx1] : 0.0f;
        }
    }
    __syncthreads();

    int pb = 0;
    for (int mt = mt0; mt < MTILES; mt += CTAS_PER_N, pb ^= 1) {
        // ---- prefetch next segment into registers ----
        const int mtn = mt + CTAS_PER_N;
        float p0 = 0.0f, p1 = 0.0f;
        if (mtn < MTILES) {
            int bidx = mtn >> 6, t0 = (mtn & 63) * BM;
            int gx0 = t0 + tid - (W_SZ - 1);
            if (gx0 >= 0) p0 = x[bidx * T_SZ + gx0];
            if (tid < 128) {
                int j = 256 + tid;
                int gx1 = t0 + j - (W_SZ - 1);
                if (j < 383 && gx1 >= 0) p1 = x[bidx * T_SZ + gx1];
            }
        }

        // ---- MMA mainloop: K=256 (16 k-steps), 8 m-tiles, 2 n-tiles ----
        float acc[8][2][4];
        #pragma unroll
        for (int m = 0; m < 8; m++)
            #pragma unroll
            for (int n = 0; n < 2; n++)
                #pragma unroll
                for (int c = 0; c < 4; c++) acc[m][n][c] = 0.0f;

        const float* sg = seg[pb];
        const int base0 = r4 + 2 * q;

        // Toeplitz A: av[j] = half2(seg[base0 + 16*ks + 8j .. +1])
        uint32_t av[17];
        #pragma unroll
        for (int j = 0; j < 17; j++) av[j] = ldcvt(sg + base0 + 8 * j);

        #pragma unroll
        for (int ks = 0; ks < 16; ks++) {
            uint32_t b0, b1, b2, b3;
            ldmatrix_x4(b0, b1, b2, b3, baddr0 + (uint32_t)(ks * 32));
            #pragma unroll
            for (int m = 0; m < 8; m++) {
                mma16816(acc[m][0], av[2*m], av[2*m+1], av[2*m+1], av[2*m+2], b0, b1);
                mma16816(acc[m][1], av[2*m], av[2*m+1], av[2*m+1], av[2*m+2], b2, b3);
            }
            if (ks < 15) {
                #pragma unroll
                for (int j = 0; j < 15; j++) av[j] = av[j + 2];
                av[15] = ldcvt(sg + base0 + 16 * (ks + 1) + 120);
                av[16] = ldcvt(sg + base0 + 16 * (ks + 1) + 128);
            }
        }

        // ---- store prefetched segment into alternate buffer ----
        if (mtn < MTILES) {
            seg[pb ^ 1][tid] = p0;
            if (tid < 128) seg[pb ^ 1][256 + tid] = p1;
        }

        // ---- epilogue: bias + STG.128 (permuted cols are contiguous) ----
        const size_t rowb = (size_t)mt * BM + (size_t)r4;
        #pragma unroll
        for (int m = 0; m < 8; m++) {
            float* o0 = out + (rowb + 16 * m) * EMB + colb;
            float* o1 = o0 + 8 * EMB;
            float4 v0 = make_float4(acc[m][0][0] + bias4.x, acc[m][0][1] + bias4.y,
                                    acc[m][1][0] + bias4.z, acc[m][1][1] + bias4.w);
            float4 v1 = make_float4(acc[m][0][2] + bias4.x, acc[m][0][3] + bias4.y,
                                    acc[m][1][2] + bias4.z, acc[m][1][3] + bias4.w);
            *reinterpret_cast<float4*>(o0) = v0;
            *reinterpret_cast<float4*>(o1) = v1;
        }
        __syncthreads();   // seg[pb^1] visible; seg[pb] free for next prefetch
    }
}

// ============================================================
extern "C" void kernel_launch(void* const* d_in, const int* in_sizes, int n_in,
                              void* d_out, int out_size) {
    const float* x  = nullptr;
    const float* wt = nullptr;
    const float* bs = nullptr;
    for (int i = 0; i < n_in; i++) {
        if (in_sizes[i] == B_SZ * T_SZ)        x  = (const float*)d_in[i];
        else if (in_sizes[i] == EMB * NFEAT)   wt = (const float*)d_in[i];
        else if (in_sizes[i] == EMB)           bs = (const float*)d_in[i];
    }

    weff_kernel<<<EMB, 256>>>(wt);

    cudaFuncSetAttribute(fft_gemm_kernel,
                         cudaFuncAttributeMaxDynamicSharedMemorySize, SMEM_TOTAL);
    fft_gemm_kernel<<<GRID, THREADS, SMEM_TOTAL>>>(x, bs, (float*)d_out);
}